// round 1
// baseline (speedup 1.0000x reference)
#include <cuda_runtime.h>
#include <cstdint>
#include <climits>

#define ROWS      8192
#define COLS      32768
#define K_TOP     32
#define NTHREADS  512
#define CAND_CAP  4096
#define PRE_THRESH 2.0f

// Monotone map: float -> uint32 preserving order (larger float -> larger uint)
__device__ __forceinline__ unsigned fmap(float f) {
    unsigned b = __float_as_uint(f);
    return (b & 0x80000000u) ? ~b : (b | 0x80000000u);
}

__global__ __launch_bounds__(NTHREADS) void topk_kernel(
    const float* __restrict__ x, float* __restrict__ out)
{
    __shared__ float    s_cv[CAND_CAP];   // candidate values
    __shared__ int      s_ci[CAND_CAP];   // candidate indices (within row)
    __shared__ int      s_cnt;
    __shared__ int      s_hist[256];
    __shared__ unsigned s_prefix;
    __shared__ int      s_want;
    __shared__ int      s_ceq;

    const int row = blockIdx.x;
    const size_t row_off = (size_t)row * COLS;
    const float4* __restrict__ xin  = reinterpret_cast<const float4*>(x + row_off);
    float4* __restrict__       zout = reinterpret_cast<float4*>(out + row_off);
    const int tid = threadIdx.x;

    if (tid == 0) s_cnt = 0;
    __syncthreads();

    // ---------------- Phase 1: stream read + zero-fill + candidate gather ---
    const float4 z4 = make_float4(0.f, 0.f, 0.f, 0.f);
    #pragma unroll
    for (int k = 0; k < COLS / 4 / NTHREADS; k++) {
        const int j = tid + k * NTHREADS;
        float4 v = __ldcs(&xin[j]);
        __stcs(&zout[j], z4);
        const int base = j * 4;
        if (v.x >= PRE_THRESH) { int p = atomicAdd(&s_cnt, 1); if (p < CAND_CAP) { s_cv[p] = v.x; s_ci[p] = base + 0; } }
        if (v.y >= PRE_THRESH) { int p = atomicAdd(&s_cnt, 1); if (p < CAND_CAP) { s_cv[p] = v.y; s_ci[p] = base + 1; } }
        if (v.z >= PRE_THRESH) { int p = atomicAdd(&s_cnt, 1); if (p < CAND_CAP) { s_cv[p] = v.z; s_ci[p] = base + 2; } }
        if (v.w >= PRE_THRESH) { int p = atomicAdd(&s_cnt, 1); if (p < CAND_CAP) { s_cv[p] = v.w; s_ci[p] = base + 3; } }
    }
    __syncthreads();

    const int cnt = s_cnt;
    const bool fast = (cnt >= K_TOP) && (cnt <= CAND_CAP);

    if (fast) {
        // ---------- Phase 2: exact radix select (MSB, 8-bit digits) over candidates
        unsigned prefix = 0;
        int want = K_TOP;
        #pragma unroll
        for (int shift = 24; shift >= 0; shift -= 8) {
            for (int d = tid; d < 256; d += NTHREADS) s_hist[d] = 0;
            __syncthreads();
            for (int j = tid; j < cnt; j += NTHREADS) {
                unsigned u = fmap(s_cv[j]);
                if (shift == 24 || (u >> (shift + 8)) == prefix)
                    atomicAdd(&s_hist[(u >> shift) & 255], 1);
            }
            __syncthreads();
            if (tid == 0) {
                int acc = 0;
                int d = 255;
                for (; d >= 0; d--) {
                    if (acc + s_hist[d] >= want) break;
                    acc += s_hist[d];
                }
                if (d < 0) d = 0;  // defensive; cannot happen when cnt >= want
                s_prefix = (prefix << 8) | (unsigned)d;
                s_want   = want - acc;
                s_ceq    = s_hist[d];
            }
            __syncthreads();
            prefix = s_prefix;
            want   = s_want;
        }
        const unsigned T   = prefix;   // exact mapped value of the K-th largest
        const int     need = want;     // how many == T to include
        const int     ceq  = s_ceq;    // how many == T exist among candidates

        // ---------- Phase 3: scatter winners over the zeroed row ----------
        for (int j = tid; j < cnt; j += NTHREADS) {
            unsigned u = fmap(s_cv[j]);
            if (u > T || (u == T && need == ceq))
                out[row_off + s_ci[j]] = fmaxf(s_cv[j], 0.f);
        }
        if (need != ceq && tid == 0) {
            // ties at the boundary: take the smallest indices first (top_k semantics)
            for (int t = 0; t < need; t++) {
                int best = INT_MAX, bj = -1;
                for (int j = 0; j < cnt; j++) {
                    if (fmap(s_cv[j]) == T && s_ci[j] < best) { best = s_ci[j]; bj = j; }
                }
                if (bj >= 0) {
                    out[row_off + best] = fmaxf(s_cv[bj], 0.f);
                    s_ci[bj] = INT_MAX;  // mark taken
                }
            }
        }
    } else {
        // ---------- Fallback: full filtered radix select from global -------
        // (correct for arbitrary input; never triggered for this dataset)
        unsigned prefix = 0;
        int want = K_TOP;
        for (int shift = 24; shift >= 0; shift -= 8) {
            for (int d = tid; d < 256; d += NTHREADS) s_hist[d] = 0;
            __syncthreads();
            for (int j = tid; j < COLS; j += NTHREADS) {
                unsigned u = fmap(x[row_off + j]);
                if (shift == 24 || (u >> (shift + 8)) == prefix)
                    atomicAdd(&s_hist[(u >> shift) & 255], 1);
            }
            __syncthreads();
            if (tid == 0) {
                int acc = 0;
                int d = 255;
                for (; d >= 0; d--) {
                    if (acc + s_hist[d] >= want) break;
                    acc += s_hist[d];
                }
                if (d < 0) d = 0;
                s_prefix = (prefix << 8) | (unsigned)d;
                s_want   = want - acc;
                s_ceq    = s_hist[d];
            }
            __syncthreads();
            prefix = s_prefix;
            want   = s_want;
        }
        const unsigned T   = prefix;
        const int     need = want;
        const int     ceq  = s_ceq;

        for (int j = tid; j < COLS; j += NTHREADS) {
            float v = x[row_off + j];
            unsigned u = fmap(v);
            if (u > T || (u == T && need == ceq))
                out[row_off + j] = fmaxf(v, 0.f);
        }
        if (need != ceq && tid == 0) {
            int taken = 0;
            for (int j = 0; j < COLS && taken < need; j++) {
                float v = x[row_off + j];
                if (fmap(v) == T) { out[row_off + j] = fmaxf(v, 0.f); taken++; }
            }
        }
    }
}

extern "C" void kernel_launch(void* const* d_in, const int* in_sizes, int n_in,
                              void* d_out, int out_size)
{
    const float* x = (const float*)d_in[0];
    float* out = (float*)d_out;
    topk_kernel<<<ROWS, NTHREADS>>>(x, out);
}

// round 2
// speedup vs baseline: 1.1177x; 1.1177x over previous
#include <cuda_runtime.h>
#include <cstdint>

#define ROWS        8192
#define COLS        32768
#define K_TOP       32
#define PRE_THRESH  2.0f

#define SEGS_PER_ROW 4
#define SEG          (COLS / SEGS_PER_ROW)   // 8192 floats per CTA
#define STH          512                      // stream kernel threads
#define SEG_ITERS    (SEG / 4 / STH)          // 4 float4 iters per thread
#define SEG_CAP      512                      // per-segment candidate cap (mean ~186)
#define CAND_CAP     1536                     // per-row candidate cap (mean ~745)
#define QTH          256                      // select kernel threads

// Global scratch (zero-initialized at module load; kernel 2 resets counters)
__device__ unsigned long long g_cand[(size_t)ROWS * CAND_CAP];  // ~100 MB
__device__ int                g_cnt[ROWS];

// Monotone map: float -> uint32, order-preserving (larger float -> larger uint)
__device__ __forceinline__ unsigned fmap(float f) {
    unsigned b = __float_as_uint(f);
    return (b & 0x80000000u) ? ~b : (b | 0x80000000u);
}
__device__ __forceinline__ float unfmap(unsigned u) {
    unsigned b = (u & 0x80000000u) ? (u ^ 0x80000000u) : ~u;
    return __uint_as_float(b);
}
// key: value desc, index asc tiebreak; unique per element -> exact top-K, no ties
__device__ __forceinline__ unsigned long long make_key(float v, int idx) {
    return ((unsigned long long)fmap(v) << 32) | (unsigned)(~idx);
}

// ---------------------------------------------------------------------------
// Kernel 1: pure streaming pass. Read x, write zeros, gather rare candidates.
// ---------------------------------------------------------------------------
__global__ __launch_bounds__(STH) void stream_kernel(
    const float* __restrict__ x, float* __restrict__ out)
{
    __shared__ int s_cnt;
    __shared__ int s_base;
    __shared__ unsigned long long s_cand[SEG_CAP];

    const int seg_id = blockIdx.x;
    const int row = seg_id >> 2;          // SEGS_PER_ROW == 4
    const int seg = seg_id & 3;
    const size_t base = (size_t)row * COLS + (size_t)seg * SEG;
    const int tid = threadIdx.x;

    if (tid == 0) s_cnt = 0;
    __syncthreads();

    const float4* __restrict__ xin = reinterpret_cast<const float4*>(x + base);
    float4* __restrict__       zo  = reinterpret_cast<float4*>(out + base);
    const float4 z4 = make_float4(0.f, 0.f, 0.f, 0.f);

    #pragma unroll
    for (int k = 0; k < SEG_ITERS; k++) {
        const int j = tid + k * STH;
        float4 v = __ldcs(&xin[j]);
        __stcs(&zo[j], z4);
        const int gidx = seg * SEG + j * 4;   // index within row
        if (v.x >= PRE_THRESH) { int p = atomicAdd(&s_cnt, 1); if (p < SEG_CAP) s_cand[p] = make_key(v.x, gidx + 0); }
        if (v.y >= PRE_THRESH) { int p = atomicAdd(&s_cnt, 1); if (p < SEG_CAP) s_cand[p] = make_key(v.y, gidx + 1); }
        if (v.z >= PRE_THRESH) { int p = atomicAdd(&s_cnt, 1); if (p < SEG_CAP) s_cand[p] = make_key(v.z, gidx + 2); }
        if (v.w >= PRE_THRESH) { int p = atomicAdd(&s_cnt, 1); if (p < SEG_CAP) s_cand[p] = make_key(v.w, gidx + 3); }
    }
    __syncthreads();

    const int cnt = s_cnt;
    if (tid == 0) {
        // On segment overflow, poison the row count so kernel 2 falls back.
        int add = (cnt > SEG_CAP) ? (CAND_CAP + 1 + cnt) : cnt;
        s_base = atomicAdd(&g_cnt[row], add);
    }
    __syncthreads();

    const int wcnt = min(cnt, SEG_CAP);
    const int b = s_base;
    for (int j = tid; j < wcnt; j += STH) {
        const int pos = b + j;
        if (pos < CAND_CAP)
            g_cand[(size_t)row * CAND_CAP + pos] = s_cand[j];
    }
}

// ---------------------------------------------------------------------------
// Kernel 2: exact top-K radix select over candidates (64-bit unique keys),
// scatter winners. Fallback: full re-scan of the row (correctness only).
// ---------------------------------------------------------------------------
__global__ __launch_bounds__(QTH) void select_kernel(
    const float* __restrict__ x, float* __restrict__ out)
{
    __shared__ unsigned long long s_cand[CAND_CAP];
    __shared__ int s_hist[256];
    __shared__ int s_suf[256];
    __shared__ int s_digit, s_want, s_done;

    const int row = blockIdx.x;
    const size_t row_off = (size_t)row * COLS;
    const int tid = threadIdx.x;

    const int cnt = g_cnt[row];
    const bool fast = (cnt >= K_TOP) && (cnt <= CAND_CAP);
    const int n = fast ? cnt : COLS;

    if (fast) {
        for (int j = tid; j < cnt; j += QTH)
            s_cand[j] = g_cand[(size_t)row * CAND_CAP + j];
    }
    __syncthreads();

    unsigned long long prefix = 0, T = 0;
    int want = K_TOP;
    bool done = false;

    for (int shift = 56; shift >= 0 && !done; shift -= 8) {
        s_hist[tid] = 0;
        __syncthreads();
        for (int j = tid; j < n; j += QTH) {
            unsigned long long key = fast ? s_cand[j] : make_key(x[row_off + j], j);
            if (shift == 56 || (key >> (shift + 8)) == prefix)
                atomicAdd(&s_hist[(int)((key >> shift) & 255)], 1);
        }
        __syncthreads();

        // parallel inclusive suffix-sum over 256 bins
        s_suf[tid] = s_hist[tid];
        __syncthreads();
        #pragma unroll
        for (int off = 1; off < 256; off <<= 1) {
            int add = (tid + off < 256) ? s_suf[tid + off] : 0;
            __syncthreads();
            s_suf[tid] += add;
            __syncthreads();
        }
        {
            const int sufd  = s_suf[tid];
            const int sufd1 = (tid < 255) ? s_suf[tid + 1] : 0;
            if (sufd >= want && sufd1 < want) {
                s_digit = tid;
                s_want  = want - sufd1;
                // all keys with this digit are selected -> threshold resolved
                s_done  = ((want - sufd1) == (sufd - sufd1)) ? 1 : 0;
            }
        }
        __syncthreads();
        prefix = (prefix << 8) | (unsigned long long)s_digit;
        want = s_want;
        done = (s_done != 0);
        if (done || shift == 0) T = prefix << shift;
        __syncthreads();
    }

    // Scatter: keys are unique, so key >= T selects exactly K_TOP entries.
    for (int j = tid; j < n; j += QTH) {
        unsigned long long key = fast ? s_cand[j] : make_key(x[row_off + j], j);
        if (key >= T) {
            const int idx = (int)(~(unsigned)key) & (COLS - 1);
            const float v = unfmap((unsigned)(key >> 32));
            out[row_off + idx] = fmaxf(v, 0.f);
        }
    }

    // Reset counter for deterministic graph replays.
    __syncthreads();
    if (tid == 0) g_cnt[row] = 0;
}

extern "C" void kernel_launch(void* const* d_in, const int* in_sizes, int n_in,
                              void* d_out, int out_size)
{
    const float* x = (const float*)d_in[0];
    float* out = (float*)d_out;
    stream_kernel<<<ROWS * SEGS_PER_ROW, STH>>>(x, out);
    select_kernel<<<ROWS, QTH>>>(x, out);
}

// round 3
// speedup vs baseline: 1.1381x; 1.0182x over previous
#include <cuda_runtime.h>
#include <cstdint>

#define ROWS        8192
#define COLS        32768
#define K_TOP       32
#define PRE_THRESH  2.0f

#define SEGS_PER_ROW 4
#define SEG          (COLS / SEGS_PER_ROW)
#define STH          512
#define SEG_ITERS    (SEG / 4 / STH)
#define SEG_CAP      512
#define CAND_CAP     1536
#define QTH          256
#define SMALL_CAP    256

// Global scratch (zero-initialized at load; select kernel resets counters)
__device__ unsigned long long g_cand[(size_t)ROWS * CAND_CAP];
__device__ int                g_cnt[ROWS];

__device__ __forceinline__ unsigned fmap(float f) {
    unsigned b = __float_as_uint(f);
    return (b & 0x80000000u) ? ~b : (b | 0x80000000u);
}
__device__ __forceinline__ float unfmap(unsigned u) {
    unsigned b = (u & 0x80000000u) ? (u ^ 0x80000000u) : ~u;
    return __uint_as_float(b);
}
// unique key: value desc, index asc tiebreak (matches jax.lax.top_k)
__device__ __forceinline__ unsigned long long make_key(float v, int idx) {
    return ((unsigned long long)fmap(v) << 32) | (unsigned)(~idx);
}

// ---------------------------------------------------------------------------
// Kernel 1: pure streaming pass (unchanged — at the LTS ceiling)
// ---------------------------------------------------------------------------
__global__ __launch_bounds__(STH) void stream_kernel(
    const float* __restrict__ x, float* __restrict__ out)
{
    __shared__ int s_cnt;
    __shared__ int s_base;
    __shared__ unsigned long long s_cand[SEG_CAP];

    const int seg_id = blockIdx.x;
    const int row = seg_id >> 2;
    const int seg = seg_id & 3;
    const size_t base = (size_t)row * COLS + (size_t)seg * SEG;
    const int tid = threadIdx.x;

    if (tid == 0) s_cnt = 0;
    __syncthreads();

    const float4* __restrict__ xin = reinterpret_cast<const float4*>(x + base);
    float4* __restrict__       zo  = reinterpret_cast<float4*>(out + base);
    const float4 z4 = make_float4(0.f, 0.f, 0.f, 0.f);

    #pragma unroll
    for (int k = 0; k < SEG_ITERS; k++) {
        const int j = tid + k * STH;
        float4 v = __ldcs(&xin[j]);
        __stcs(&zo[j], z4);
        const int gidx = seg * SEG + j * 4;
        if (v.x >= PRE_THRESH) { int p = atomicAdd(&s_cnt, 1); if (p < SEG_CAP) s_cand[p] = make_key(v.x, gidx + 0); }
        if (v.y >= PRE_THRESH) { int p = atomicAdd(&s_cnt, 1); if (p < SEG_CAP) s_cand[p] = make_key(v.y, gidx + 1); }
        if (v.z >= PRE_THRESH) { int p = atomicAdd(&s_cnt, 1); if (p < SEG_CAP) s_cand[p] = make_key(v.z, gidx + 2); }
        if (v.w >= PRE_THRESH) { int p = atomicAdd(&s_cnt, 1); if (p < SEG_CAP) s_cand[p] = make_key(v.w, gidx + 3); }
    }
    __syncthreads();

    const int cnt = s_cnt;
    if (tid == 0) {
        int add = (cnt > SEG_CAP) ? (CAND_CAP + 1 + cnt) : cnt;
        s_base = atomicAdd(&g_cnt[row], add);
    }
    __syncthreads();

    const int wcnt = min(cnt, SEG_CAP);
    const int b = s_base;
    for (int j = tid; j < wcnt; j += STH) {
        const int pos = b + j;
        if (pos < CAND_CAP)
            g_cand[(size_t)row * CAND_CAP + pos] = s_cand[j];
    }
}

// ---------------------------------------------------------------------------
// Kernel 2: exact top-K select. Warp-shuffle suffix scan (2 barriers/pass),
// early compaction + O(c^2) rank-select once the boundary set is small.
// ---------------------------------------------------------------------------
__global__ __launch_bounds__(QTH) void select_kernel(
    const float* __restrict__ x, float* __restrict__ out)
{
    __shared__ unsigned long long s_cand[CAND_CAP];
    __shared__ int s_hist[256];
    __shared__ int s_wtot[8];
    __shared__ int s_digit, s_want, s_bcnt, s_scnt;
    __shared__ unsigned long long s_small[SMALL_CAP];
    __shared__ unsigned long long s_T;

    const int row = blockIdx.x;
    const size_t row_off = (size_t)row * COLS;
    const int tid  = threadIdx.x;
    const int lane = tid & 31;
    const int warp = tid >> 5;

    const int cnt = g_cnt[row];
    const bool fast = (cnt >= K_TOP) && (cnt <= CAND_CAP);
    const int n = fast ? cnt : COLS;

    if (fast) {
        for (int j = tid; j < cnt; j += QTH)
            s_cand[j] = g_cand[(size_t)row * CAND_CAP + j];
    }
    __syncthreads();

    unsigned long long prefix = 0, T = 0;
    int want = K_TOP;

    for (int shift = 56; shift >= 0; shift -= 8) {
        s_hist[tid] = 0;
        if (tid == 0) s_scnt = 0;
        __syncthreads();

        for (int j = tid; j < n; j += QTH) {
            unsigned long long key = fast ? s_cand[j] : make_key(x[row_off + j], j);
            if (shift == 56 || (key >> (shift + 8)) == prefix)
                atomicAdd(&s_hist[(int)((key >> shift) & 255)], 1);
        }
        __syncthreads();

        // inclusive suffix-sum over 256 bins: warp shuffles + tiny cross-warp fix
        const int h = s_hist[tid];
        int v = h;
        #pragma unroll
        for (int off = 1; off < 32; off <<= 1) {
            int o = __shfl_down_sync(0xffffffffu, v, off);
            if (lane + off < 32) v += o;
        }
        if (lane == 0) s_wtot[warp] = v;   // total of this warp's 32 bins
        __syncthreads();
        int add = 0;
        #pragma unroll
        for (int w2 = 0; w2 < 8; w2++)
            if (w2 > warp) add += s_wtot[w2];
        const int suf  = v + add;      // sum of bins [tid..255]
        const int suf1 = suf - h;      // sum of bins [tid+1..255]
        if (suf >= want && suf1 < want) {
            s_digit = tid;
            s_want  = want - suf1;
            s_bcnt  = h;
        }
        __syncthreads();

        prefix = (prefix << 8) | (unsigned long long)s_digit;
        want   = s_want;
        const int c = s_bcnt;

        if (want == c) {               // whole boundary bin selected -> exact T
            T = prefix << shift;
            break;
        }
        if (c <= SMALL_CAP) {          // compact boundary keys, rank-select
            for (int j = tid; j < n; j += QTH) {
                unsigned long long key = fast ? s_cand[j] : make_key(x[row_off + j], j);
                if ((key >> shift) == prefix) {
                    int p = atomicAdd(&s_scnt, 1);
                    s_small[p] = key;
                }
            }
            __syncthreads();
            if (tid < c) {
                const unsigned long long mykey = s_small[tid];
                int rank = 0;
                for (int j = 0; j < c; j++)
                    rank += (s_small[j] > mykey);
                if (rank == want - 1) s_T = mykey;  // keys unique -> exactly one
            }
            __syncthreads();
            T = s_T;
            break;
        }
        __syncthreads();
        // else: continue radix refinement (terminates: at shift=0 keys unique)
    }

    // Scatter: keys unique, key >= T selects exactly K_TOP entries.
    for (int j = tid; j < n; j += QTH) {
        unsigned long long key = fast ? s_cand[j] : make_key(x[row_off + j], j);
        if (key >= T) {
            const int idx = (int)(~(unsigned)key) & (COLS - 1);
            const float v = unfmap((unsigned)(key >> 32));
            out[row_off + idx] = fmaxf(v, 0.f);
        }
    }

    __syncthreads();
    if (tid == 0) g_cnt[row] = 0;   // deterministic graph replays
}

extern "C" void kernel_launch(void* const* d_in, const int* in_sizes, int n_in,
                              void* d_out, int out_size)
{
    const float* x = (const float*)d_in[0];
    float* out = (float*)d_out;
    stream_kernel<<<ROWS * SEGS_PER_ROW, STH>>>(x, out);
    select_kernel<<<ROWS, QTH>>>(x, out);
}